// round 12
// baseline (speedup 1.0000x reference)
#include <cuda_runtime.h>
#include <cuda_bf16.h>

// Global scalar accumulator. Zero at module load for the correctness run;
// kl_finalize_kernel resets it to 0.0 after consuming it, so every graph
// replay starts from identical state (self-restoring, deterministic).
__device__ double g_accum;

__device__ __forceinline__ float kl_elem(float mp, float lsp, float mq, float lsq) {
    // elem = (lsq - lsp) + exp(lsp - lsq) + (mq-mp)^2 * exp(-lsq)
    float t = lsp - lsq;
    float dz = mq - mp;
    return -t + __expf(t) + dz * dz * __expf(-lsq);
}

__global__ void __launch_bounds__(256, 8)
kl_reduce_kernel(const float4* __restrict__ mp,
                 const float4* __restrict__ lsp,
                 const float4* __restrict__ mq,
                 const float4* __restrict__ lsq,
                 int n4) {
    // PDL: allow the dependent finalize kernel to begin launching now; its
    // cudaGridDependencySynchronize() still waits for ALL of this grid's
    // memory writes, so correctness is unaffected.
    if (threadIdx.x == 0)
        cudaTriggerProgrammaticLaunchCompletion();

    float sum = 0.0f;
    int idx = blockIdx.x * blockDim.x + threadIdx.x;
    int stride = gridDim.x * blockDim.x;

    // Best-measured streaming loop (unchanged since R2): 4 independent
    // LDG.E.128 per iteration, 32 regs, grid-stride interleave.
    for (int i = idx; i < n4; i += stride) {
        float4 a = __ldcs(&mp[i]);
        float4 p = __ldcs(&lsp[i]);
        float4 b = __ldcs(&mq[i]);
        float4 q = __ldcs(&lsq[i]);
        sum += kl_elem(a.x, p.x, b.x, q.x);
        sum += kl_elem(a.y, p.y, b.y, q.y);
        sum += kl_elem(a.z, p.z, b.z, q.z);
        sum += kl_elem(a.w, p.w, b.w, q.w);
    }

    // Warp reduction
    #pragma unroll
    for (int o = 16; o > 0; o >>= 1)
        sum += __shfl_xor_sync(0xFFFFFFFFu, sum, o);

    // Block reduction via shared memory (8 warps)
    __shared__ float wsums[8];
    int wid = threadIdx.x >> 5;
    int lid = threadIdx.x & 31;
    if (lid == 0) wsums[wid] = sum;
    __syncthreads();

    if (wid == 0) {
        float v = (lid < (blockDim.x >> 5)) ? wsums[lid] : 0.0f;
        #pragma unroll
        for (int o = 4; o > 0; o >>= 1)
            v += __shfl_xor_sync(0xFFFFFFFFu, v, o);
        if (lid == 0)
            atomicAdd(&g_accum, (double)v);
    }
}

__global__ void kl_finalize_kernel(float* out, double inv_nsamples, double d) {
    // Wait until the upstream (reduce) grid's writes are globally visible.
    cudaGridDependencySynchronize();
    out[0] = (float)(0.5 * (g_accum * inv_nsamples - d));
    g_accum = 0.0;   // restore state for the next graph replay
}

extern "C" void kernel_launch(void* const* d_in, const int* in_sizes, int n_in,
                              void* d_out, int out_size) {
    const float4* mp  = (const float4*)d_in[0];
    const float4* lsp = (const float4*)d_in[1];
    const float4* mq  = (const float4*)d_in[2];
    const float4* lsq = (const float4*)d_in[3];
    float* out = (float*)d_out;

    const int n = in_sizes[0];          // 29,491,200 elements (b=2, d=3, 160*192*160)
    const int n4 = n / 4;               // float4 count
    const int d_chan = 3;               // channel dim (shape[1])
    const long long n_samples = (long long)n / d_chan;  // b*D*H*W

    const int threads = 256;
    const int blocks = 148 * 16;        // 2368 blocks, grid-stride

    kl_reduce_kernel<<<blocks, threads>>>(mp, lsp, mq, lsq, n4);

    // Finalize with programmatic dependent launch: its launch overlaps the
    // reduce kernel's tail; data dependence enforced in-kernel.
    cudaLaunchConfig_t cfg = {};
    cfg.gridDim = dim3(1, 1, 1);
    cfg.blockDim = dim3(1, 1, 1);
    cfg.dynamicSmemBytes = 0;
    cfg.stream = 0;
    cudaLaunchAttribute attr;
    attr.id = cudaLaunchAttributeProgrammaticStreamSerialization;
    attr.val.programmaticStreamSerializationAllowed = 1;
    cfg.attrs = &attr;
    cfg.numAttrs = 1;
    double inv_ns = 1.0 / (double)n_samples;
    double dchan = (double)d_chan;
    cudaLaunchKernelEx(&cfg, kl_finalize_kernel, out, inv_ns, dchan);
}